// round 8
// baseline (speedup 1.0000x reference)
#include <cuda_runtime.h>
#include <cstdint>
#include <math.h>

#define S_LEN 2048
#define HID   1024
#define NH    16
#define HD    64
#define BATCH 2
#define ROWS  (BATCH * S_LEN)   // 4096

typedef unsigned long long u64;

// -------- scratch (static __device__ arrays; no allocation allowed) --------
__device__ float g_qkv[(size_t)ROWS * 3 * HID];  // [4096][3072]
__device__ float g_att[(size_t)ROWS * HID];      // [4096][1024]
__device__ float g_cos[S_LEN * 32];
__device__ float g_sin[S_LEN * 32];

// ======================= packed f32x2 helpers ==============================
__device__ __forceinline__ u64 pack2(float x, float y) {
    u64 r; asm("mov.b64 %0, {%1,%2};" : "=l"(r) : "f"(x), "f"(y)); return r;
}
__device__ __forceinline__ void fma2(u64& d, u64 a, u64 b) {
    asm("fma.rn.f32x2 %0, %1, %2, %0;" : "+l"(d) : "l"(a), "l"(b));
}
__device__ __forceinline__ u64 mul2(u64 a, u64 b) {
    u64 r; asm("mul.rn.f32x2 %0, %1, %2;" : "=l"(r) : "l"(a), "l"(b)); return r;
}
__device__ __forceinline__ float2 unpack2(u64 v) {
    float2 r; asm("mov.b64 {%0,%1}, %2;" : "=f"(r.x), "=f"(r.y) : "l"(v)); return r;
}
__device__ __forceinline__ int bswz(int blk) { return blk ^ ((blk >> 3) & 7); }

// ====================== f32x2 SGEMM v4 (128x128x16) ========================
// A m-major in smem -> natural (row2r,row2r+1) u64 pairs via LDS.128.
// B duplicated (v,v) pairs, 4-word blocks XOR-swizzled -> conflict-free.
// Inner loop: 6 LDS.128 + 32 FFMA2, zero packing movs.
__global__ __launch_bounds__(256, 2) void sgemm4(
    const float* __restrict__ A, const float* __restrict__ B,
    float* __restrict__ C, int M, int N, int K)
{
    __shared__ __align__(16) float As[16][136];    // [k][m]
    __shared__ __align__(16) float Bsd[16][264];   // dup pairs, block-swizzled

    const int tid = threadIdx.x;
    const int tx = tid & 15, ty = tid >> 4;
    const int m0 = blockIdx.y * 128, n0 = blockIdx.x * 128;

    // loader mapping
    const int ar = tid & 127, akc = (tid >> 7) << 3;   // A: row ar, 8 k's
    const int br = tid >> 5,  bnc = (tid & 31) << 2;   // B: k-rows br/br+8, 4 cols
    const int bb0 = bswz(bnc >> 1), bb1 = bswz((bnc >> 1) + 1);  // u64 idx = 2*blk{+1}
    const float* Agp = A + (size_t)(m0 + ar) * K + akc;
    const float* Bgp = B + (size_t)br * N + n0 + bnc;

    // compute-side B word offsets (4 blocks of 4 words)
    const int cb0 = bswz(4 * tx + 0) << 2;
    const int cb1 = bswz(4 * tx + 1) << 2;
    const int cb2 = bswz(4 * tx + 2) << 2;
    const int cb3 = bswz(4 * tx + 3) << 2;

    u64 acc[4][8];   // [row-pair][col]
#pragma unroll
    for (int r = 0; r < 4; r++)
#pragma unroll
        for (int c = 0; c < 8; c++) acc[r][c] = pack2(0.f, 0.f);

    float4 pa0, pa1, pb0, pb1;
    const int T = K >> 4;

    pa0 = *(const float4*)(Agp);
    pa1 = *(const float4*)(Agp + 4);
    pb0 = *(const float4*)(Bgp);
    pb1 = *(const float4*)(Bgp + (size_t)8 * N);

    for (int t = 0; t < T; t++) {
        __syncthreads();
        {
            const float av[8] = {pa0.x, pa0.y, pa0.z, pa0.w, pa1.x, pa1.y, pa1.z, pa1.w};
#pragma unroll
            for (int e = 0; e < 8; e++) As[akc + e][ar] = av[e];
            u64* B0 = (u64*)&Bsd[br][0];
            u64* B1 = (u64*)&Bsd[br + 8][0];
            B0[2 * bb0]     = pack2(pb0.x, pb0.x);
            B0[2 * bb0 + 1] = pack2(pb0.y, pb0.y);
            B0[2 * bb1]     = pack2(pb0.z, pb0.z);
            B0[2 * bb1 + 1] = pack2(pb0.w, pb0.w);
            B1[2 * bb0]     = pack2(pb1.x, pb1.x);
            B1[2 * bb0 + 1] = pack2(pb1.y, pb1.y);
            B1[2 * bb1]     = pack2(pb1.z, pb1.z);
            B1[2 * bb1 + 1] = pack2(pb1.w, pb1.w);
        }
        __syncthreads();

        if (t + 1 < T) {
            const int k0 = (t + 1) << 4;
            pa0 = *(const float4*)(Agp + k0);
            pa1 = *(const float4*)(Agp + k0 + 4);
            pb0 = *(const float4*)(Bgp + (size_t)k0 * N);
            pb1 = *(const float4*)(Bgp + (size_t)(k0 + 8) * N);
        }

#pragma unroll
        for (int kk = 0; kk < 16; kk++) {
            ulonglong2 a01 = *(const ulonglong2*)&As[kk][ty * 8];
            ulonglong2 a23 = *(const ulonglong2*)&As[kk][ty * 8 + 4];
            ulonglong2 b0 = *(const ulonglong2*)&Bsd[kk][cb0];
            ulonglong2 b1 = *(const ulonglong2*)&Bsd[kk][cb1];
            ulonglong2 b2 = *(const ulonglong2*)&Bsd[kk][cb2];
            ulonglong2 b3 = *(const ulonglong2*)&Bsd[kk][cb3];
            const u64 ap[4] = {a01.x, a01.y, a23.x, a23.y};
            const u64 bp[8] = {b0.x, b0.y, b1.x, b1.y, b2.x, b2.y, b3.x, b3.y};
#pragma unroll
            for (int r = 0; r < 4; r++)
#pragma unroll
                for (int c = 0; c < 8; c++) fma2(acc[r][c], ap[r], bp[c]);
        }
    }

#pragma unroll
    for (int r = 0; r < 4; r++) {
        float* c0r = C + (size_t)(m0 + ty * 8 + 2 * r) * N + n0 + tx * 8;
        float* c1r = c0r + N;
        float2 p0 = unpack2(acc[r][0]), p1 = unpack2(acc[r][1]);
        float2 p2 = unpack2(acc[r][2]), p3 = unpack2(acc[r][3]);
        float2 p4 = unpack2(acc[r][4]), p5 = unpack2(acc[r][5]);
        float2 p6 = unpack2(acc[r][6]), p7 = unpack2(acc[r][7]);
        *(float4*)(c0r)     = make_float4(p0.x, p1.x, p2.x, p3.x);
        *(float4*)(c0r + 4) = make_float4(p4.x, p5.x, p6.x, p7.x);
        *(float4*)(c1r)     = make_float4(p0.y, p1.y, p2.y, p3.y);
        *(float4*)(c1r + 4) = make_float4(p4.y, p5.y, p6.y, p7.y);
    }
}

// ============================ RoPE tables ==================================
__global__ void rope_tables_kernel()
{
    int idx = blockIdx.x * blockDim.x + threadIdx.x;
    if (idx >= S_LEN * 32) return;
    int s = idx >> 5, j = idx & 31;
    double inv = exp(-((double)j / 32.0) * log(160000.0));
    double ang = (double)s * inv;
    g_cos[idx] = (float)cos(ang);
    g_sin[idx] = (float)sin(ang);
}

// ======================= RoPE apply (in-place on qkv) ======================
__global__ __launch_bounds__(256) void rope_apply_kernel()
{
    int idx = blockIdx.x * blockDim.x + threadIdx.x;
    if (idx >= ROWS * 1024) return;
    int row  = idx >> 10;
    int rem  = idx & 1023;
    int t    = rem >> 9;
    int rem2 = rem & 511;
    int h    = rem2 >> 5;
    int j    = rem2 & 31;
    int s    = row & (S_LEN - 1);

    size_t base = (size_t)row * 3072 + (size_t)t * HID + h * HD;
    float x1 = g_qkv[base + j];
    float x2 = g_qkv[base + j + 32];
    float c  = g_cos[s * 32 + j];
    float sn = g_sin[s * 32 + j];
    g_qkv[base + j]      = x1 * c - x2 * sn;
    g_qkv[base + j + 32] = x2 * c + x1 * sn;
}

// ================= fused causal flash attention v3 =========================
// 128 q-rows per CTA, 64-col k tiles. 256 thr: ty=tid>>3 (32), tx=tid&7 (8).
// Thread tile: 4 q-rows (i0=4ty) x 8 k-cols (c0=8tx).
#define AQT 0
#define AKT 8192
#define AVS 12288
#define APT 16640
#define ATTN_F 24832          // 99328 bytes

__global__ __launch_bounds__(256, 2) void attn3_kernel(
    const float* __restrict__ qkv, float* __restrict__ out)
{
    extern __shared__ __align__(16) float sm[];
    float* Qt = sm + AQT;
    float* Kt = sm + AKT;
    float* Vs = sm + AVS;
    float* Pt = sm + APT;

    const int tid = threadIdx.x;
    const int tx = tid & 7, ty = tid >> 3;
    const int i0 = ty * 4, c0 = tx * 8;
    const int sK = (tx >> 2) << 2;
    const int qt = gridDim.x - 1 - blockIdx.x;     // heavy tiles first
    const int bh = blockIdx.y;
    const int b = bh >> 4, h = bh & 15;
    const int q0 = qt * 128;
    const size_t rowbase = (size_t)b * S_LEN;
    const int qoff = h * HD, koff = HID + h * HD, voff = 2 * HID + h * HD;

    {
        const int frq = tid & 127, fgq = tid >> 7;
        const float* qp = qkv + (rowbase + q0 + frq) * 3072 + qoff + fgq * 32;
#pragma unroll
        for (int q = 0; q < 8; q++) {
            float4 v = *(const float4*)(qp + 4 * q);
            int d = fgq * 32 + 4 * q;
            Qt[(d + 0) * 128 + frq] = v.x; Qt[(d + 1) * 128 + frq] = v.y;
            Qt[(d + 2) * 128 + frq] = v.z; Qt[(d + 3) * 128 + frq] = v.w;
        }
    }

    const int fr = tid & 63, fg = tid >> 6;
    const int jswz = fr ^ ((((fr >> 5) & 1)) << 2);
    const int vcs  = (fg >> 1) << 2;

    float mreg[4], lreg[4], alpha[4];
    u64 O[4][4];
#pragma unroll
    for (int r = 0; r < 4; r++) {
        mreg[r] = -INFINITY; lreg[r] = 0.f;
#pragma unroll
        for (int c = 0; c < 4; c++) O[r][c] = pack2(0.f, 0.f);
    }

    for (int j0 = 0; j0 <= q0 + 64; j0 += 64) {
        __syncthreads();
        {
            const float* kp = qkv + (rowbase + j0 + fr) * 3072 + koff + fg * 16;
#pragma unroll
            for (int q = 0; q < 4; q++) {
                float4 v = *(const float4*)(kp + 4 * q);
                int d = fg * 16 + 4 * q;
                Kt[(d + 0) * 64 + jswz] = v.x; Kt[(d + 1) * 64 + jswz] = v.y;
                Kt[(d + 2) * 64 + jswz] = v.z; Kt[(d + 3) * 64 + jswz] = v.w;
            }
            const float* vp = qkv + (rowbase + j0 + fr) * 3072 + voff + fg * 16;
#pragma unroll
            for (int q = 0; q < 4; q++) {
                int c = fg * 16 + 4 * q;
                *(float4*)&Vs[fr * 68 + (c ^ vcs)] = *(const float4*)(vp + 4 * q);
            }
        }
        __syncthreads();

        u64 sac[4][4];
#pragma unroll
        for (int r = 0; r < 4; r++)
#pragma unroll
            for (int c = 0; c < 4; c++) sac[r][c] = pack2(0.f, 0.f);
#pragma unroll 4
        for (int d = 0; d < 64; d++) {
            float4 qv = *(const float4*)&Qt[d * 128 + i0];
            ulonglong2 k0 = *(const ulonglong2*)&Kt[d * 64 + (c0 ^ sK)];
            ulonglong2 k1 = *(const ulonglong2*)&Kt[d * 64 + ((c0 + 4) ^ sK)];
            const float qa[4] = {qv.x, qv.y, qv.z, qv.w};
#pragma unroll
            for (int r = 0; r < 4; r++) {
                u64 qp2 = pack2(qa[r], qa[r]);
                fma2(sac[r][0], qp2, k0.x);
                fma2(sac[r][1], qp2, k0.y);
                fma2(sac[r][2], qp2, k1.x);
                fma2(sac[r][3], qp2, k1.y);
            }
        }

        const bool maskt = (j0 + 63 > q0);
        float ps[4][8];
#pragma unroll
        for (int r = 0; r < 4; r++) {
            float sv[8];
#pragma unroll
            for (int c = 0; c < 4; c++) {
                float2 v = unpack2(sac[r][c]);
                sv[2 * c] = v.x * 0.125f; sv[2 * c + 1] = v.y * 0.125f;
            }
            if (maskt) {
                int rowg = q0 + i0 + r;
#pragma unroll
                for (int cc = 0; cc < 8; cc++)
                    if (j0 + c0 + cc > rowg) sv[cc] = -1e9f;
            }
            float ml = sv[0];
#pragma unroll
            for (int cc = 1; cc < 8; cc++) ml = fmaxf(ml, sv[cc]);
            ml = fmaxf(ml, __shfl_xor_sync(0xffffffffu, ml, 1));
            ml = fmaxf(ml, __shfl_xor_sync(0xffffffffu, ml, 2));
            ml = fmaxf(ml, __shfl_xor_sync(0xffffffffu, ml, 4));
            float mn = fmaxf(mreg[r], ml);
            float a = __expf(mreg[r] - mn);
            mreg[r] = mn; alpha[r] = a;
            float rs = 0.f;
#pragma unroll
            for (int cc = 0; cc < 8; cc++) { ps[r][cc] = __expf(sv[cc] - mn); rs += ps[r][cc]; }
            rs += __shfl_xor_sync(0xffffffffu, rs, 1);
            rs += __shfl_xor_sync(0xffffffffu, rs, 2);
            rs += __shfl_xor_sync(0xffffffffu, rs, 4);
            lreg[r] = lreg[r] * a + rs;
        }
        {
            const int ip = i0 ^ (tx << 2);
#pragma unroll
            for (int cc = 0; cc < 8; cc++)
                *(float4*)&Pt[(c0 + cc) * 128 + ip] =
                    make_float4(ps[0][cc], ps[1][cc], ps[2][cc], ps[3][cc]);
        }
#pragma unroll
        for (int r = 0; r < 4; r++) {
            u64 a2 = pack2(alpha[r], alpha[r]);
#pragma unroll
            for (int c = 0; c < 4; c++) O[r][c] = mul2(O[r][c], a2);
        }
        __syncthreads();

#pragma unroll
        for (int jo = 0; jo < 8; jo++) {
            const int sp = jo << 2;
#pragma unroll
            for (int ji = 0; ji < 8; ji++) {
                const int j = jo * 8 + ji;
                float4 pv = *(const float4*)&Pt[j * 128 + (i0 ^ sp)];
                ulonglong2 v0 = *(const ulonglong2*)&Vs[j * 68 + (c0 ^ sK)];
                ulonglong2 v1 = *(const ulonglong2*)&Vs[j * 68 + ((c0 + 4) ^ sK)];
                const float pa[4] = {pv.x, pv.y, pv.z, pv.w};
#pragma unroll
                for (int r = 0; r < 4; r++) {
                    u64 pp = pack2(pa[r], pa[r]);
                    fma2(O[r][0], pp, v0.x);
                    fma2(O[r][1], pp, v0.y);
                    fma2(O[r][2], pp, v1.x);
                    fma2(O[r][3], pp, v1.y);
                }
            }
        }
    }

#pragma unroll
    for (int r = 0; r < 4; r++) {
        float linv = 1.0f / lreg[r];
        float2 v0 = unpack2(O[r][0]), v1 = unpack2(O[r][1]);
        float2 v2 = unpack2(O[r][2]), v3 = unpack2(O[r][3]);
        float* op = out + (rowbase + q0 + i0 + r) * HID + h * HD + c0;
        *(float4*)(op)     = make_float4(v0.x * linv, v0.y * linv, v1.x * linv, v1.y * linv);
        *(float4*)(op + 4) = make_float4(v2.x * linv, v2.y * linv, v3.x * linv, v3.y * linv);
    }
}

// ================================ launch ===================================
extern "C" void kernel_launch(void* const* d_in, const int* in_sizes, int n_in,
                              void* d_out, int out_size)
{
    const float* hidden = (const float*)d_in[0];
    const float* Wqkv = (const float*)d_in[2];
    const float* Wo   = (const float*)d_in[3];
    float* out = (float*)d_out;

    float *qkv_ptr, *att_ptr;
    cudaGetSymbolAddress((void**)&qkv_ptr, g_qkv);
    cudaGetSymbolAddress((void**)&att_ptr, g_att);

    rope_tables_kernel<<<(S_LEN * 32 + 255) / 256, 256>>>();

    sgemm4<<<dim3(3 * HID / 128, ROWS / 128), 256>>>(hidden, Wqkv, qkv_ptr, ROWS, 3 * HID, HID);

    rope_apply_kernel<<<(ROWS * 1024) / 256, 256>>>();

    const int SMEM = ATTN_F * 4;
    cudaFuncSetAttribute(attn3_kernel, cudaFuncAttributeMaxDynamicSharedMemorySize, SMEM);
    dim3 g2(S_LEN / 128, BATCH * NH);
    attn3_kernel<<<g2, 256, SMEM>>>(qkv_ptr, att_ptr);

    sgemm4<<<dim3(HID / 128, ROWS / 128), 256>>>(att_ptr, Wo, out, ROWS, HID, HID);
}

// round 9
// speedup vs baseline: 1.1404x; 1.1404x over previous
#include <cuda_runtime.h>
#include <cstdint>
#include <math.h>

#define S_LEN 2048
#define HID   1024
#define NH    16
#define HD    64
#define BATCH 2
#define ROWS  (BATCH * S_LEN)   // 4096

typedef unsigned long long u64;

// -------- scratch (static __device__ arrays; no allocation allowed) --------
__device__ float g_qkv[(size_t)ROWS * 3 * HID];  // [4096][3072]
__device__ float g_att[(size_t)ROWS * HID];      // [4096][1024]
__device__ float g_cos[S_LEN * 32];
__device__ float g_sin[S_LEN * 32];

// ======================= packed f32x2 helpers ==============================
__device__ __forceinline__ u64 pack2(float x, float y) {
    u64 r; asm("mov.b64 %0, {%1,%2};" : "=l"(r) : "f"(x), "f"(y)); return r;
}
__device__ __forceinline__ void fma2(u64& d, u64 a, u64 b) {
    asm("fma.rn.f32x2 %0, %1, %2, %0;" : "+l"(d) : "l"(a), "l"(b));
}
__device__ __forceinline__ u64 mul2(u64 a, u64 b) {
    u64 r; asm("mul.rn.f32x2 %0, %1, %2;" : "=l"(r) : "l"(a), "l"(b)); return r;
}
__device__ __forceinline__ float2 unpack2(u64 v) {
    float2 r; asm("mov.b64 {%0,%1}, %2;" : "=f"(r.x), "=f"(r.y) : "l"(v)); return r;
}

// ====================== f32x2 SGEMM (128x128x16) ===========================
// sgemm2 (round-6 best) + B col-XOR swizzle to kill the 2-way LDS conflict.
__global__ __launch_bounds__(256, 2) void sgemm5(
    const float* __restrict__ A, const float* __restrict__ B,
    float* __restrict__ C, int M, int N, int K)
{
    __shared__ __align__(16) float As[16][132];   // 16B-aligned rows
    __shared__ __align__(16) float Bs[16][128];   // col-swizzled

    const int tid = threadIdx.x;
    const int tx = tid & 15, ty = tid >> 4;
    const int m0 = blockIdx.y * 128, n0 = blockIdx.x * 128;
    const int s2 = ((tx >> 2) & 1) << 2;          // compute-side col XOR

    const int ar = tid & 127, akc = (tid >> 7) << 3;
    const int br = tid >> 5,  bnc = (tid & 31) << 2;
    const int bns = bnc ^ ((((bnc >> 5) & 1)) << 2);   // store-side col XOR
    const float* Agp = A + (size_t)(m0 + ar) * K + akc;
    const float* Bgp = B + (size_t)br * N + n0 + bnc;

    u64 acc[8][4];
#pragma unroll
    for (int r = 0; r < 8; r++)
#pragma unroll
        for (int c = 0; c < 4; c++) acc[r][c] = pack2(0.f, 0.f);

    float4 pa0, pa1, pb0, pb1;
    const int T = K >> 4;

    pa0 = *(const float4*)(Agp);
    pa1 = *(const float4*)(Agp + 4);
    pb0 = *(const float4*)(Bgp);
    pb1 = *(const float4*)(Bgp + (size_t)8 * N);

    for (int t = 0; t < T; t++) {
        __syncthreads();
        {
            const float av[8] = {pa0.x, pa0.y, pa0.z, pa0.w, pa1.x, pa1.y, pa1.z, pa1.w};
#pragma unroll
            for (int e = 0; e < 8; e++) As[akc + e][ar] = av[e];
            *(float4*)&Bs[br][bns]     = pb0;
            *(float4*)&Bs[br + 8][bns] = pb1;
        }
        __syncthreads();

        if (t + 1 < T) {
            const int k0 = (t + 1) << 4;
            pa0 = *(const float4*)(Agp + k0);
            pa1 = *(const float4*)(Agp + k0 + 4);
            pb0 = *(const float4*)(Bgp + (size_t)k0 * N);
            pb1 = *(const float4*)(Bgp + (size_t)(k0 + 8) * N);
        }

#pragma unroll
        for (int kk = 0; kk < 16; kk++) {
            float4 a0 = *(const float4*)&As[kk][ty * 8];
            float4 a1 = *(const float4*)&As[kk][ty * 8 + 4];
            float4 b0 = *(const float4*)&Bs[kk][(tx * 8) ^ s2];
            float4 b1 = *(const float4*)&Bs[kk][(tx * 8 + 4) ^ s2];
            u64 bp[4] = {pack2(b0.x, b0.y), pack2(b0.z, b0.w),
                         pack2(b1.x, b1.y), pack2(b1.z, b1.w)};
            const float av[8] = {a0.x, a0.y, a0.z, a0.w, a1.x, a1.y, a1.z, a1.w};
#pragma unroll
            for (int r = 0; r < 8; r++) {
                u64 ap = pack2(av[r], av[r]);
#pragma unroll
                for (int c = 0; c < 4; c++) fma2(acc[r][c], ap, bp[c]);
            }
        }
    }

#pragma unroll
    for (int r = 0; r < 8; r++) {
        float* crow = C + (size_t)(m0 + ty * 8 + r) * N + n0 + tx * 8;
        float2 v0 = unpack2(acc[r][0]), v1 = unpack2(acc[r][1]);
        float2 v2 = unpack2(acc[r][2]), v3 = unpack2(acc[r][3]);
        *(float4*)(crow)     = make_float4(v0.x, v0.y, v1.x, v1.y);
        *(float4*)(crow + 4) = make_float4(v2.x, v2.y, v3.x, v3.y);
    }
}

// ============================ RoPE tables ==================================
__global__ void rope_tables_kernel()
{
    int idx = blockIdx.x * blockDim.x + threadIdx.x;
    if (idx >= S_LEN * 32) return;
    int s = idx >> 5, j = idx & 31;
    double inv = exp(-((double)j / 32.0) * log(160000.0));
    double ang = (double)s * inv;
    g_cos[idx] = (float)cos(ang);
    g_sin[idx] = (float)sin(ang);
}

// ======================= RoPE apply (in-place on qkv) ======================
__global__ __launch_bounds__(256) void rope_apply_kernel()
{
    int idx = blockIdx.x * blockDim.x + threadIdx.x;
    if (idx >= ROWS * 1024) return;
    int row  = idx >> 10;
    int rem  = idx & 1023;
    int t    = rem >> 9;
    int rem2 = rem & 511;
    int h    = rem2 >> 5;
    int j    = rem2 & 31;
    int s    = row & (S_LEN - 1);

    size_t base = (size_t)row * 3072 + (size_t)t * HID + h * HD;
    float x1 = g_qkv[base + j];
    float x2 = g_qkv[base + j + 32];
    float c  = g_cos[s * 32 + j];
    float sn = g_sin[s * 32 + j];
    g_qkv[base + j]      = x1 * c - x2 * sn;
    g_qkv[base + j + 32] = x2 * c + x1 * sn;
}

// ================= fused causal flash attention v3 =========================
// 128 q-rows per CTA, 64-col k tiles. 256 thr: ty=tid>>3 (32), tx=tid&7 (8).
// Thread tile: 4 q-rows (i0=4ty) x 8 k-cols (c0=8tx). Normal qt order.
#define AQT 0
#define AKT 8192
#define AVS 12288
#define APT 16640
#define ATTN_F 24832          // 99328 bytes

__global__ __launch_bounds__(256, 2) void attn3_kernel(
    const float* __restrict__ qkv, float* __restrict__ out)
{
    extern __shared__ __align__(16) float sm[];
    float* Qt = sm + AQT;
    float* Kt = sm + AKT;
    float* Vs = sm + AVS;
    float* Pt = sm + APT;

    const int tid = threadIdx.x;
    const int tx = tid & 7, ty = tid >> 3;
    const int i0 = ty * 4, c0 = tx * 8;
    const int sK = (tx >> 2) << 2;
    const int qt = blockIdx.x;
    const int bh = blockIdx.y;
    const int b = bh >> 4, h = bh & 15;
    const int q0 = qt * 128;
    const size_t rowbase = (size_t)b * S_LEN;
    const int qoff = h * HD, koff = HID + h * HD, voff = 2 * HID + h * HD;

    {
        const int frq = tid & 127, fgq = tid >> 7;
        const float* qp = qkv + (rowbase + q0 + frq) * 3072 + qoff + fgq * 32;
#pragma unroll
        for (int q = 0; q < 8; q++) {
            float4 v = *(const float4*)(qp + 4 * q);
            int d = fgq * 32 + 4 * q;
            Qt[(d + 0) * 128 + frq] = v.x; Qt[(d + 1) * 128 + frq] = v.y;
            Qt[(d + 2) * 128 + frq] = v.z; Qt[(d + 3) * 128 + frq] = v.w;
        }
    }

    const int fr = tid & 63, fg = tid >> 6;
    const int jswz = fr ^ ((((fr >> 5) & 1)) << 2);
    const int vcs  = (fg >> 1) << 2;

    float mreg[4], lreg[4], alpha[4];
    u64 O[4][4];
#pragma unroll
    for (int r = 0; r < 4; r++) {
        mreg[r] = -INFINITY; lreg[r] = 0.f;
#pragma unroll
        for (int c = 0; c < 4; c++) O[r][c] = pack2(0.f, 0.f);
    }

    for (int j0 = 0; j0 <= q0 + 64; j0 += 64) {
        __syncthreads();
        {
            const float* kp = qkv + (rowbase + j0 + fr) * 3072 + koff + fg * 16;
#pragma unroll
            for (int q = 0; q < 4; q++) {
                float4 v = *(const float4*)(kp + 4 * q);
                int d = fg * 16 + 4 * q;
                Kt[(d + 0) * 64 + jswz] = v.x; Kt[(d + 1) * 64 + jswz] = v.y;
                Kt[(d + 2) * 64 + jswz] = v.z; Kt[(d + 3) * 64 + jswz] = v.w;
            }
            const float* vp = qkv + (rowbase + j0 + fr) * 3072 + voff + fg * 16;
#pragma unroll
            for (int q = 0; q < 4; q++) {
                int c = fg * 16 + 4 * q;
                *(float4*)&Vs[fr * 68 + (c ^ vcs)] = *(const float4*)(vp + 4 * q);
            }
        }
        __syncthreads();

        u64 sac[4][4];
#pragma unroll
        for (int r = 0; r < 4; r++)
#pragma unroll
            for (int c = 0; c < 4; c++) sac[r][c] = pack2(0.f, 0.f);
#pragma unroll 4
        for (int d = 0; d < 64; d++) {
            float4 qv = *(const float4*)&Qt[d * 128 + i0];
            ulonglong2 k0 = *(const ulonglong2*)&Kt[d * 64 + (c0 ^ sK)];
            ulonglong2 k1 = *(const ulonglong2*)&Kt[d * 64 + ((c0 + 4) ^ sK)];
            const float qa[4] = {qv.x, qv.y, qv.z, qv.w};
#pragma unroll
            for (int r = 0; r < 4; r++) {
                u64 qp2 = pack2(qa[r], qa[r]);
                fma2(sac[r][0], qp2, k0.x);
                fma2(sac[r][1], qp2, k0.y);
                fma2(sac[r][2], qp2, k1.x);
                fma2(sac[r][3], qp2, k1.y);
            }
        }

        const bool maskt = (j0 + 63 > q0);
        float ps[4][8];
#pragma unroll
        for (int r = 0; r < 4; r++) {
            float sv[8];
#pragma unroll
            for (int c = 0; c < 4; c++) {
                float2 v = unpack2(sac[r][c]);
                sv[2 * c] = v.x * 0.125f; sv[2 * c + 1] = v.y * 0.125f;
            }
            if (maskt) {
                int rowg = q0 + i0 + r;
#pragma unroll
                for (int cc = 0; cc < 8; cc++)
                    if (j0 + c0 + cc > rowg) sv[cc] = -1e9f;
            }
            float ml = sv[0];
#pragma unroll
            for (int cc = 1; cc < 8; cc++) ml = fmaxf(ml, sv[cc]);
            ml = fmaxf(ml, __shfl_xor_sync(0xffffffffu, ml, 1));
            ml = fmaxf(ml, __shfl_xor_sync(0xffffffffu, ml, 2));
            ml = fmaxf(ml, __shfl_xor_sync(0xffffffffu, ml, 4));
            float mn = fmaxf(mreg[r], ml);
            float a = __expf(mreg[r] - mn);
            mreg[r] = mn; alpha[r] = a;
            float rs = 0.f;
#pragma unroll
            for (int cc = 0; cc < 8; cc++) { ps[r][cc] = __expf(sv[cc] - mn); rs += ps[r][cc]; }
            rs += __shfl_xor_sync(0xffffffffu, rs, 1);
            rs += __shfl_xor_sync(0xffffffffu, rs, 2);
            rs += __shfl_xor_sync(0xffffffffu, rs, 4);
            lreg[r] = lreg[r] * a + rs;
        }
        {
            const int ip = i0 ^ (tx << 2);
#pragma unroll
            for (int cc = 0; cc < 8; cc++)
                *(float4*)&Pt[(c0 + cc) * 128 + ip] =
                    make_float4(ps[0][cc], ps[1][cc], ps[2][cc], ps[3][cc]);
        }
#pragma unroll
        for (int r = 0; r < 4; r++) {
            u64 a2 = pack2(alpha[r], alpha[r]);
#pragma unroll
            for (int c = 0; c < 4; c++) O[r][c] = mul2(O[r][c], a2);
        }
        __syncthreads();

#pragma unroll
        for (int jo = 0; jo < 8; jo++) {
            const int sp = jo << 2;
#pragma unroll
            for (int ji = 0; ji < 8; ji++) {
                const int j = jo * 8 + ji;
                float4 pv = *(const float4*)&Pt[j * 128 + (i0 ^ sp)];
                ulonglong2 v0 = *(const ulonglong2*)&Vs[j * 68 + (c0 ^ sK)];
                ulonglong2 v1 = *(const ulonglong2*)&Vs[j * 68 + ((c0 + 4) ^ sK)];
                const float pa[4] = {pv.x, pv.y, pv.z, pv.w};
#pragma unroll
                for (int r = 0; r < 4; r++) {
                    u64 pp = pack2(pa[r], pa[r]);
                    fma2(O[r][0], pp, v0.x);
                    fma2(O[r][1], pp, v0.y);
                    fma2(O[r][2], pp, v1.x);
                    fma2(O[r][3], pp, v1.y);
                }
            }
        }
    }

#pragma unroll
    for (int r = 0; r < 4; r++) {
        float linv = 1.0f / lreg[r];
        float2 v0 = unpack2(O[r][0]), v1 = unpack2(O[r][1]);
        float2 v2 = unpack2(O[r][2]), v3 = unpack2(O[r][3]);
        float* op = out + (rowbase + q0 + i0 + r) * HID + h * HD + c0;
        *(float4*)(op)     = make_float4(v0.x * linv, v0.y * linv, v1.x * linv, v1.y * linv);
        *(float4*)(op + 4) = make_float4(v2.x * linv, v2.y * linv, v3.x * linv, v3.y * linv);
    }
}

// ================================ launch ===================================
extern "C" void kernel_launch(void* const* d_in, const int* in_sizes, int n_in,
                              void* d_out, int out_size)
{
    const float* hidden = (const float*)d_in[0];
    const float* Wqkv = (const float*)d_in[2];
    const float* Wo   = (const float*)d_in[3];
    float* out = (float*)d_out;

    float *qkv_ptr, *att_ptr;
    cudaGetSymbolAddress((void**)&qkv_ptr, g_qkv);
    cudaGetSymbolAddress((void**)&att_ptr, g_att);

    rope_tables_kernel<<<(S_LEN * 32 + 255) / 256, 256>>>();

    sgemm5<<<dim3(3 * HID / 128, ROWS / 128), 256>>>(hidden, Wqkv, qkv_ptr, ROWS, 3 * HID, HID);

    rope_apply_kernel<<<(ROWS * 1024) / 256, 256>>>();

    const int SMEM = ATTN_F * 4;
    cudaFuncSetAttribute(attn3_kernel, cudaFuncAttributeMaxDynamicSharedMemorySize, SMEM);
    dim3 g2(S_LEN / 128, BATCH * NH);
    attn3_kernel<<<g2, 256, SMEM>>>(qkv_ptr, att_ptr);

    sgemm5<<<dim3(HID / 128, ROWS / 128), 256>>>(att_ptr, Wo, out, ROWS, HID, HID);
}

// round 10
// speedup vs baseline: 1.2632x; 1.1077x over previous
#include <cuda_runtime.h>
#include <cstdint>
#include <math.h>

#define S_LEN 2048
#define HID   1024
#define NH    16
#define HD    64
#define BATCH 2
#define ROWS  (BATCH * S_LEN)   // 4096
#define NT    (S_LEN / 128)     // 16 q-tiles

typedef unsigned long long u64;

// -------- scratch (static __device__ arrays; no allocation allowed) --------
__device__ float g_qkv[(size_t)ROWS * 3 * HID];  // [4096][3072]
__device__ float g_att[(size_t)ROWS * HID];      // [4096][1024]
__device__ float g_cos[S_LEN * 32];
__device__ float g_sin[S_LEN * 32];

// ======================= packed f32x2 helpers ==============================
__device__ __forceinline__ u64 pack2(float x, float y) {
    u64 r; asm("mov.b64 %0, {%1,%2};" : "=l"(r) : "f"(x), "f"(y)); return r;
}
__device__ __forceinline__ void fma2(u64& d, u64 a, u64 b) {
    asm("fma.rn.f32x2 %0, %1, %2, %0;" : "+l"(d) : "l"(a), "l"(b));
}
__device__ __forceinline__ u64 mul2(u64 a, u64 b) {
    u64 r; asm("mul.rn.f32x2 %0, %1, %2;" : "=l"(r) : "l"(a), "l"(b)); return r;
}
__device__ __forceinline__ float2 unpack2(u64 v) {
    float2 r; asm("mov.b64 {%0,%1}, %2;" : "=f"(r.x), "=f"(r.y) : "l"(v)); return r;
}

// ====================== f32x2 SGEMM (128x128x16) ===========================
__global__ __launch_bounds__(256, 2) void sgemm5(
    const float* __restrict__ A, const float* __restrict__ B,
    float* __restrict__ C, int M, int N, int K)
{
    __shared__ __align__(16) float As[16][132];
    __shared__ __align__(16) float Bs[16][128];

    const int tid = threadIdx.x;
    const int tx = tid & 15, ty = tid >> 4;
    const int m0 = blockIdx.y * 128, n0 = blockIdx.x * 128;
    const int s2 = ((tx >> 2) & 1) << 2;

    const int ar = tid & 127, akc = (tid >> 7) << 3;
    const int br = tid >> 5,  bnc = (tid & 31) << 2;
    const int bns = bnc ^ ((((bnc >> 5) & 1)) << 2);
    const float* Agp = A + (size_t)(m0 + ar) * K + akc;
    const float* Bgp = B + (size_t)br * N + n0 + bnc;

    u64 acc[8][4];
#pragma unroll
    for (int r = 0; r < 8; r++)
#pragma unroll
        for (int c = 0; c < 4; c++) acc[r][c] = pack2(0.f, 0.f);

    float4 pa0, pa1, pb0, pb1;
    const int T = K >> 4;

    pa0 = *(const float4*)(Agp);
    pa1 = *(const float4*)(Agp + 4);
    pb0 = *(const float4*)(Bgp);
    pb1 = *(const float4*)(Bgp + (size_t)8 * N);

    for (int t = 0; t < T; t++) {
        __syncthreads();
        {
            const float av[8] = {pa0.x, pa0.y, pa0.z, pa0.w, pa1.x, pa1.y, pa1.z, pa1.w};
#pragma unroll
            for (int e = 0; e < 8; e++) As[akc + e][ar] = av[e];
            *(float4*)&Bs[br][bns]     = pb0;
            *(float4*)&Bs[br + 8][bns] = pb1;
        }
        __syncthreads();

        if (t + 1 < T) {
            const int k0 = (t + 1) << 4;
            pa0 = *(const float4*)(Agp + k0);
            pa1 = *(const float4*)(Agp + k0 + 4);
            pb0 = *(const float4*)(Bgp + (size_t)k0 * N);
            pb1 = *(const float4*)(Bgp + (size_t)(k0 + 8) * N);
        }

#pragma unroll
        for (int kk = 0; kk < 16; kk++) {
            float4 a0 = *(const float4*)&As[kk][ty * 8];
            float4 a1 = *(const float4*)&As[kk][ty * 8 + 4];
            float4 b0 = *(const float4*)&Bs[kk][(tx * 8) ^ s2];
            float4 b1 = *(const float4*)&Bs[kk][(tx * 8 + 4) ^ s2];
            u64 bp[4] = {pack2(b0.x, b0.y), pack2(b0.z, b0.w),
                         pack2(b1.x, b1.y), pack2(b1.z, b1.w)};
            const float av[8] = {a0.x, a0.y, a0.z, a0.w, a1.x, a1.y, a1.z, a1.w};
#pragma unroll
            for (int r = 0; r < 8; r++) {
                u64 ap = pack2(av[r], av[r]);
#pragma unroll
                for (int c = 0; c < 4; c++) fma2(acc[r][c], ap, bp[c]);
            }
        }
    }

#pragma unroll
    for (int r = 0; r < 8; r++) {
        float* crow = C + (size_t)(m0 + ty * 8 + r) * N + n0 + tx * 8;
        float2 v0 = unpack2(acc[r][0]), v1 = unpack2(acc[r][1]);
        float2 v2 = unpack2(acc[r][2]), v3 = unpack2(acc[r][3]);
        *(float4*)(crow)     = make_float4(v0.x, v0.y, v1.x, v1.y);
        *(float4*)(crow + 4) = make_float4(v2.x, v2.y, v3.x, v3.y);
    }
}

// ============================ RoPE tables ==================================
__global__ void rope_tables_kernel()
{
    int idx = blockIdx.x * blockDim.x + threadIdx.x;
    if (idx >= S_LEN * 32) return;
    int s = idx >> 5, j = idx & 31;
    double inv = exp(-((double)j / 32.0) * log(160000.0));
    double ang = (double)s * inv;
    g_cos[idx] = (float)cos(ang);
    g_sin[idx] = (float)sin(ang);
}

// ======================= RoPE apply (in-place on qkv) ======================
__global__ __launch_bounds__(256) void rope_apply_kernel()
{
    int idx = blockIdx.x * blockDim.x + threadIdx.x;
    if (idx >= ROWS * 1024) return;
    int row  = idx >> 10;
    int rem  = idx & 1023;
    int t    = rem >> 9;
    int rem2 = rem & 511;
    int h    = rem2 >> 5;
    int j    = rem2 & 31;
    int s    = row & (S_LEN - 1);

    size_t base = (size_t)row * 3072 + (size_t)t * HID + h * HD;
    float x1 = g_qkv[base + j];
    float x2 = g_qkv[base + j + 32];
    float c  = g_cos[s * 32 + j];
    float sn = g_sin[s * 32 + j];
    g_qkv[base + j]      = x1 * c - x2 * sn;
    g_qkv[base + j + 32] = x2 * c + x1 * sn;
}

// ============ fused causal flash attention v4 (triangle-balanced) ==========
// Each CTA handles q-tiles {blockIdx.x, NT-1-blockIdx.x}: uniform 34 k-iters.
#define AQT 0
#define AKT 8192
#define AVS 12288
#define APT 16640
#define ATTN_F 24832          // 99328 bytes

__global__ __launch_bounds__(256, 2) void attn4_kernel(
    const float* __restrict__ qkv, float* __restrict__ out)
{
    extern __shared__ __align__(16) float sm[];
    float* Qt = sm + AQT;
    float* Kt = sm + AKT;
    float* Vs = sm + AVS;
    float* Pt = sm + APT;

    const int tid = threadIdx.x;
    const int tx = tid & 7, ty = tid >> 3;
    const int i0 = ty * 4, c0 = tx * 8;
    const int sK = (tx >> 2) << 2;
    const int bh = blockIdx.y;
    const int b = bh >> 4, h = bh & 15;
    const size_t rowbase = (size_t)b * S_LEN;
    const int qoff = h * HD, koff = HID + h * HD, voff = 2 * HID + h * HD;

    const int frq = tid & 127, fgq = tid >> 7;
    const int fr = tid & 63, fg = tid >> 6;
    const int jswz = fr ^ ((((fr >> 5) & 1)) << 2);
    const int vcs  = (fg >> 1) << 2;

#pragma unroll 1
    for (int pass = 0; pass < 2; pass++) {
        const int qt = pass ? (NT - 1 - (int)blockIdx.x) : (int)blockIdx.x;
        const int q0 = qt * 128;

        // Q fill (safe: all threads past last S-loop of previous pass)
        {
            const float* qp = qkv + (rowbase + q0 + frq) * 3072 + qoff + fgq * 32;
#pragma unroll
            for (int q = 0; q < 8; q++) {
                float4 v = *(const float4*)(qp + 4 * q);
                int d = fgq * 32 + 4 * q;
                Qt[(d + 0) * 128 + frq] = v.x; Qt[(d + 1) * 128 + frq] = v.y;
                Qt[(d + 2) * 128 + frq] = v.z; Qt[(d + 3) * 128 + frq] = v.w;
            }
        }

        float mreg[4], lreg[4], alpha[4];
        u64 O[4][4];
#pragma unroll
        for (int r = 0; r < 4; r++) {
            mreg[r] = -INFINITY; lreg[r] = 0.f;
#pragma unroll
            for (int c = 0; c < 4; c++) O[r][c] = pack2(0.f, 0.f);
        }

        for (int j0 = 0; j0 <= q0 + 64; j0 += 64) {
            __syncthreads();
            {
                const float* kp = qkv + (rowbase + j0 + fr) * 3072 + koff + fg * 16;
#pragma unroll
                for (int q = 0; q < 4; q++) {
                    float4 v = *(const float4*)(kp + 4 * q);
                    int d = fg * 16 + 4 * q;
                    Kt[(d + 0) * 64 + jswz] = v.x; Kt[(d + 1) * 64 + jswz] = v.y;
                    Kt[(d + 2) * 64 + jswz] = v.z; Kt[(d + 3) * 64 + jswz] = v.w;
                }
                const float* vp = qkv + (rowbase + j0 + fr) * 3072 + voff + fg * 16;
#pragma unroll
                for (int q = 0; q < 4; q++) {
                    int c = fg * 16 + 4 * q;
                    *(float4*)&Vs[fr * 68 + (c ^ vcs)] = *(const float4*)(vp + 4 * q);
                }
            }
            __syncthreads();

            u64 sac[4][4];
#pragma unroll
            for (int r = 0; r < 4; r++)
#pragma unroll
                for (int c = 0; c < 4; c++) sac[r][c] = pack2(0.f, 0.f);
#pragma unroll 4
            for (int d = 0; d < 64; d++) {
                float4 qv = *(const float4*)&Qt[d * 128 + i0];
                ulonglong2 k0 = *(const ulonglong2*)&Kt[d * 64 + (c0 ^ sK)];
                ulonglong2 k1 = *(const ulonglong2*)&Kt[d * 64 + ((c0 + 4) ^ sK)];
                const float qa[4] = {qv.x, qv.y, qv.z, qv.w};
#pragma unroll
                for (int r = 0; r < 4; r++) {
                    u64 qp2 = pack2(qa[r], qa[r]);
                    fma2(sac[r][0], qp2, k0.x);
                    fma2(sac[r][1], qp2, k0.y);
                    fma2(sac[r][2], qp2, k1.x);
                    fma2(sac[r][3], qp2, k1.y);
                }
            }

            const bool maskt = (j0 + 63 > q0);
            float ps[4][8];
#pragma unroll
            for (int r = 0; r < 4; r++) {
                float sv[8];
#pragma unroll
                for (int c = 0; c < 4; c++) {
                    float2 v = unpack2(sac[r][c]);
                    sv[2 * c] = v.x * 0.125f; sv[2 * c + 1] = v.y * 0.125f;
                }
                if (maskt) {
                    int rowg = q0 + i0 + r;
#pragma unroll
                    for (int cc = 0; cc < 8; cc++)
                        if (j0 + c0 + cc > rowg) sv[cc] = -1e9f;
                }
                float ml = sv[0];
#pragma unroll
                for (int cc = 1; cc < 8; cc++) ml = fmaxf(ml, sv[cc]);
                ml = fmaxf(ml, __shfl_xor_sync(0xffffffffu, ml, 1));
                ml = fmaxf(ml, __shfl_xor_sync(0xffffffffu, ml, 2));
                ml = fmaxf(ml, __shfl_xor_sync(0xffffffffu, ml, 4));
                float mn = fmaxf(mreg[r], ml);
                float a = __expf(mreg[r] - mn);
                mreg[r] = mn; alpha[r] = a;
                float rs = 0.f;
#pragma unroll
                for (int cc = 0; cc < 8; cc++) { ps[r][cc] = __expf(sv[cc] - mn); rs += ps[r][cc]; }
                rs += __shfl_xor_sync(0xffffffffu, rs, 1);
                rs += __shfl_xor_sync(0xffffffffu, rs, 2);
                rs += __shfl_xor_sync(0xffffffffu, rs, 4);
                lreg[r] = lreg[r] * a + rs;
            }
            {
                const int ip = i0 ^ (tx << 2);
#pragma unroll
                for (int cc = 0; cc < 8; cc++)
                    *(float4*)&Pt[(c0 + cc) * 128 + ip] =
                        make_float4(ps[0][cc], ps[1][cc], ps[2][cc], ps[3][cc]);
            }
#pragma unroll
            for (int r = 0; r < 4; r++) {
                u64 a2 = pack2(alpha[r], alpha[r]);
#pragma unroll
                for (int c = 0; c < 4; c++) O[r][c] = mul2(O[r][c], a2);
            }
            __syncthreads();

#pragma unroll
            for (int jo = 0; jo < 8; jo++) {
                const int sp = jo << 2;
#pragma unroll
                for (int ji = 0; ji < 8; ji++) {
                    const int j = jo * 8 + ji;
                    float4 pv = *(const float4*)&Pt[j * 128 + (i0 ^ sp)];
                    ulonglong2 v0 = *(const ulonglong2*)&Vs[j * 68 + (c0 ^ sK)];
                    ulonglong2 v1 = *(const ulonglong2*)&Vs[j * 68 + ((c0 + 4) ^ sK)];
                    const float pa[4] = {pv.x, pv.y, pv.z, pv.w};
#pragma unroll
                    for (int r = 0; r < 4; r++) {
                        u64 pp = pack2(pa[r], pa[r]);
                        fma2(O[r][0], pp, v0.x);
                        fma2(O[r][1], pp, v0.y);
                        fma2(O[r][2], pp, v1.x);
                        fma2(O[r][3], pp, v1.y);
                    }
                }
            }
        }

#pragma unroll
        for (int r = 0; r < 4; r++) {
            float linv = 1.0f / lreg[r];
            float2 v0 = unpack2(O[r][0]), v1 = unpack2(O[r][1]);
            float2 v2 = unpack2(O[r][2]), v3 = unpack2(O[r][3]);
            float* op = out + (rowbase + q0 + i0 + r) * HID + h * HD + c0;
            *(float4*)(op)     = make_float4(v0.x * linv, v0.y * linv, v1.x * linv, v1.y * linv);
            *(float4*)(op + 4) = make_float4(v2.x * linv, v2.y * linv, v3.x * linv, v3.y * linv);
        }
    }
}

// ================================ launch ===================================
extern "C" void kernel_launch(void* const* d_in, const int* in_sizes, int n_in,
                              void* d_out, int out_size)
{
    const float* hidden = (const float*)d_in[0];
    const float* Wqkv = (const float*)d_in[2];
    const float* Wo   = (const float*)d_in[3];
    float* out = (float*)d_out;

    float *qkv_ptr, *att_ptr;
    cudaGetSymbolAddress((void**)&qkv_ptr, g_qkv);
    cudaGetSymbolAddress((void**)&att_ptr, g_att);

    rope_tables_kernel<<<(S_LEN * 32 + 255) / 256, 256>>>();

    sgemm5<<<dim3(3 * HID / 128, ROWS / 128), 256>>>(hidden, Wqkv, qkv_ptr, ROWS, 3 * HID, HID);

    rope_apply_kernel<<<(ROWS * 1024) / 256, 256>>>();

    const int SMEM = ATTN_F * 4;
    cudaFuncSetAttribute(attn4_kernel, cudaFuncAttributeMaxDynamicSharedMemorySize, SMEM);
    dim3 g2(NT / 2, BATCH * NH);     // (8, 32) balanced pairs
    attn4_kernel<<<g2, 256, SMEM>>>(qkv_ptr, att_ptr);

    sgemm5<<<dim3(HID / 128, ROWS / 128), 256>>>(att_ptr, Wo, out, ROWS, HID, HID);
}